// round 16
// baseline (speedup 1.0000x reference)
#include <cuda_runtime.h>
#include <cuda_fp16.h>
#include <cstdint>

#define NN_MAX 50000
#define NE_MAX 800000
#define FH 64
#define SCAN_BLK 256

// Scratch. deg|cnt|sync share one zeroed region (single memset node).
__device__ int    g_zr[2 * NN_MAX + 8];
#define G_DEG  ((float*)g_zr)
#define G_CNT  (g_zr + NN_MAX)
#define G_SYNC (g_zr + 2 * NN_MAX)   // [0..3]=scan/scatter syncs, [4,5]=gather sync
__device__ int    g_start[NN_MAX];
__device__ int    g_cursor[NN_MAX];
__device__ int    g_bsum[SCAN_BLK];
__device__ int    g_boff[SCAN_BLK];
__device__ float2 g_es[NE_MAX];         // (row-bits, norm) bucketed by dst col
__device__ uint2  g_xh[NN_MAX * 16];    // x as fp16
__device__ uint2  g_tx1h[NN_MAX * 16];  // tx1 as fp16
__device__ uint2  g_p2h[NN_MAX * 16];   // p2 as fp16
#define B_STRH 200
__device__ __half g_Wch[128 * B_STRH];  // combined weights fp16, [n][k]

__device__ __forceinline__ float tanh_fast(float x) {
    float y; asm("tanh.approx.f32 %0, %1;" : "=f"(y) : "f"(x)); return y;
}
__device__ __forceinline__ float sigmoid_fast(float x) {
    return fmaf(0.5f, tanh_fast(0.5f * x), 0.5f);
}
__device__ __forceinline__ uint2 pack_h4(float a, float b, float c, float d) {
    __half2 h0 = __floats2half2_rn(a, b);
    __half2 h1 = __floats2half2_rn(c, d);
    return make_uint2(*(uint32_t*)&h0, *(uint32_t*)&h1);
}
__device__ __forceinline__ float4 unpack_h4(uint2 u) {
    float2 a = __half22float2(*(__half2*)&u.x);
    float2 b = __half22float2(*(__half2*)&u.y);
    return make_float4(a.x, a.y, b.x, b.y);
}
__device__ __forceinline__ uint32_t smem_u32(const void* p) {
    uint32_t a;
    asm("{ .reg .u64 t; cvta.to.shared.u64 t, %1; cvt.u32.u64 %0, t; }" : "=r"(a) : "l"(p));
    return a;
}

// ---------------------------------------------------------------------------
// k_prep: deg/cnt histogram | fp16 weight build | x -> fp16  (wide parallel)
__global__ void k_prep(const int* __restrict__ row, const int* __restrict__ col,
                       const float* __restrict__ w, int ne, int n,
                       const float* __restrict__ Wxz, const float* __restrict__ Wxh,
                       const float* __restrict__ x) {
    int nbDeg = (ne + 255) >> 8;
    int bid = blockIdx.x;
    if (bid < nbDeg) {
        int e = bid * 256 + threadIdx.x;
        if (e < ne) {
            atomicAdd(G_DEG + row[e], w[e]);
            atomicAdd(G_CNT + col[e], 1);
        }
    } else if (bid < nbDeg + 96) {
        int t = (bid - nbDeg) * 256 + threadIdx.x;
        if (t < 192 * 128) {
            int k = t >> 7, j = t & 127;
            const float* W = (j < 64) ? Wxz : Wxh;
            int jj = j & 63;
            float v;
            if (k < 64)       v = W[k * 64 + jj] - W[2 * 4096 + k * 64 + jj];
            else if (k < 128) v = W[4096 + (k - 64) * 64 + jj];
            else              v = 2.f * W[2 * 4096 + (k - 128) * 64 + jj];
            g_Wch[j * B_STRH + k] = __float2half_rn(v);
        }
    } else {
        int t = (bid - nbDeg - 96) * 256 + threadIdx.x;
        if (t < n * 16) {
            float4 v = ((const float4*)x)[t];
            g_xh[t] = pack_h4(v.x, v.y, v.z, v.w);
        }
    }
}

// k_scan_scatter: exclusive scan of cnt -> start/cursor, grid sync, scatter.
__global__ void k_scan_scatter(int n, int nblk,
                               const int* __restrict__ row, const int* __restrict__ col,
                               const float* __restrict__ w, int ne) {
    __shared__ int s[SCAN_BLK];
    __shared__ int sl;
    int t = threadIdx.x;
    int i = blockIdx.x * SCAN_BLK + t;
    int v = (i < n) ? G_CNT[i] : 0;
    s[t] = v; __syncthreads();
    #pragma unroll
    for (int o = 1; o < SCAN_BLK; o <<= 1) {
        int u = (t >= o) ? s[t - o] : 0;
        __syncthreads(); s[t] += u; __syncthreads();
    }
    int incl = s[t];
    if (t == SCAN_BLK - 1) g_bsum[blockIdx.x] = incl;
    __threadfence();
    __syncthreads();
    if (t == 0) sl = (atomicAdd(G_SYNC + 0, 1) == nblk - 1) ? 1 : 0;
    __syncthreads();
    if (sl) {
        int bv = (t < nblk) ? g_bsum[t] : 0;
        s[t] = bv; __syncthreads();
        #pragma unroll
        for (int o = 1; o < SCAN_BLK; o <<= 1) {
            int u = (t >= o) ? s[t - o] : 0;
            __syncthreads(); s[t] += u; __syncthreads();
        }
        g_boff[t] = s[t] - bv;
        __threadfence();
        __syncthreads();
        if (t == 0) atomicExch(G_SYNC + 1, 1);
    }
    if (t == 0) { while (atomicAdd(G_SYNC + 1, 0) == 0) {} }
    __syncthreads();
    if (i < n) {
        int st = g_boff[blockIdx.x] + incl - v;
        g_start[i] = st;
        g_cursor[i] = st;
    }

    __threadfence();
    __syncthreads();
    if (t == 0) {
        if (atomicAdd(G_SYNC + 2, 1) == nblk - 1) atomicExch(G_SYNC + 3, 1);
        while (atomicAdd(G_SYNC + 3, 0) == 0) {}
    }
    __syncthreads();

    int stride = nblk * SCAN_BLK;
    for (int e = blockIdx.x * SCAN_BLK + t; e < ne; e += stride) {
        int r = row[e], c = col[e];
        float dr = G_DEG[r], dc = G_DEG[c];
        float ir = dr > 0.f ? rsqrtf(dr) : 0.f;
        float ic = dc > 0.f ? rsqrtf(dc) : 0.f;
        float nm = -ir * w[e] * ic;
        int pos = atomicAdd(g_cursor + c, 1);
        g_es[pos] = make_float2(__int_as_float(r), nm);
    }
}

// Persistent double gather: pass 0 (x->tx1), grid sync, pass 1 (tx1->p2).
// 16 threads/node, uint2 loads, unroll-8. 888 co-resident blocks.
#define G_FMA(e, u) do { \
    float4 _v = unpack_h4(u); \
    acc.x = fmaf((e).y, _v.x, acc.x); acc.y = fmaf((e).y, _v.y, acc.y); \
    acc.z = fmaf((e).y, _v.z, acc.z); acc.w = fmaf((e).y, _v.w, acc.w); } while (0)

__device__ __forceinline__ void gather_one(const uint2* __restrict__ src,
                                           uint2* __restrict__ dst, int idx) {
    int node = idx >> 4, h = idx & 15;
    int beg = g_start[node], cnt = G_CNT[node];
    const float2* ep = g_es + beg;
    float4 acc = make_float4(0.f, 0.f, 0.f, 0.f);
    int k = 0;
    for (; k + 8 <= cnt; k += 8) {
        float2 e0 = ep[k],     e1 = ep[k + 1], e2 = ep[k + 2], e3 = ep[k + 3];
        float2 e4 = ep[k + 4], e5 = ep[k + 5], e6 = ep[k + 6], e7 = ep[k + 7];
        uint2 u0 = src[(__float_as_int(e0.x) << 4) + h];
        uint2 u1 = src[(__float_as_int(e1.x) << 4) + h];
        uint2 u2 = src[(__float_as_int(e2.x) << 4) + h];
        uint2 u3 = src[(__float_as_int(e3.x) << 4) + h];
        uint2 u4 = src[(__float_as_int(e4.x) << 4) + h];
        uint2 u5 = src[(__float_as_int(e5.x) << 4) + h];
        uint2 u6 = src[(__float_as_int(e6.x) << 4) + h];
        uint2 u7 = src[(__float_as_int(e7.x) << 4) + h];
        G_FMA(e0, u0); G_FMA(e1, u1); G_FMA(e2, u2); G_FMA(e3, u3);
        G_FMA(e4, u4); G_FMA(e5, u5); G_FMA(e6, u6); G_FMA(e7, u7);
    }
    for (; k < cnt; ++k) {
        float2 e0 = ep[k];
        uint2 u0 = src[(__float_as_int(e0.x) << 4) + h];
        G_FMA(e0, u0);
    }
    dst[idx] = pack_h4(acc.x, acc.y, acc.z, acc.w);
}

__global__ void __launch_bounds__(256, 6)
k_gather2(int n, int nblk) {
    int t = threadIdx.x;
    int total = n * 16;
    int stride = nblk * 256;
    for (int idx = blockIdx.x * 256 + t; idx < total; idx += stride)
        gather_one(g_xh, g_tx1h, idx);

    // grid sync (all nblk blocks co-resident by launch_bounds)
    __threadfence();
    __syncthreads();
    if (t == 0) {
        if (atomicAdd(G_SYNC + 4, 1) == nblk - 1) atomicExch(G_SYNC + 5, 1);
        while (atomicAdd(G_SYNC + 5, 0) == 0) {}
    }
    __syncthreads();

    for (int idx = blockIdx.x * 256 + t; idx < total; idx += stride)
        gather_one(g_tx1h, g_p2h, idx);
}

// ---------------------------------------------------------------------------
// k_final: 64 nodes/block, cp.async staging; mma.m16n8k16.f16; tanh.approx gates.
#define A_STRH 200
#define A_STRW 100
#define NPB 64
#define SM_BZ   0
#define SM_BH   256
#define SM_WLIN 512
#define SM_A    1024
#define SMEM_BYTES (SM_A + NPB * A_STRH * 2)   // 26624

__device__ __forceinline__ void mma16(float* c, const uint32_t* a, const uint32_t* b) {
    asm volatile("mma.sync.aligned.m16n8k16.row.col.f32.f16.f16.f32 "
                 "{%0,%1,%2,%3}, {%4,%5,%6,%7}, {%8,%9}, {%0,%1,%2,%3};"
                 : "+f"(c[0]), "+f"(c[1]), "+f"(c[2]), "+f"(c[3])
                 : "r"(a[0]), "r"(a[1]), "r"(a[2]), "r"(a[3]), "r"(b[0]), "r"(b[1]));
}
__device__ __forceinline__ void cp_async8(uint32_t dst, const void* src, int srcsz) {
    asm volatile("cp.async.ca.shared.global [%0], [%1], 8, %2;"
                 :: "r"(dst), "l"(src), "r"(srcsz) : "memory");
}

__global__ void __launch_bounds__(256, 3)
k_final(const float* __restrict__ bxz, const float* __restrict__ bhz,
        const float* __restrict__ bxh, const float* __restrict__ bhh,
        const float* __restrict__ Wlin, const float* __restrict__ blin,
        float* __restrict__ out, int n) {
    extern __shared__ __align__(16) char smem[];
    float* sBz = (float*)(smem + SM_BZ);
    float* sBh = (float*)(smem + SM_BH);
    float* sWl = (float*)(smem + SM_WLIN);
    char*  As  = smem + SM_A;
    const uint32_t* Au = (const uint32_t*)As;
    const uint32_t* Bg = (const uint32_t*)g_Wch;

    int tid = threadIdx.x, wid = tid >> 5, lane = tid & 31;
    int blk = blockIdx.x;
    int base = blk * NPB;
    uint32_t sA = smem_u32(As);

    #pragma unroll
    for (int it = 0; it < 4; ++it) {
        int idx = tid + it * 256;
        int m = idx >> 4, h = idx & 15;
        int g = base + m;
        int ok = (g < n) ? 8 : 0;
        int gc = (g < n) ? g : 0;
        cp_async8(sA + m * 400 + h * 8,       g_xh   + (gc << 4) + h, ok);
        cp_async8(sA + m * 400 + 128 + h * 8, g_tx1h + (gc << 4) + h, ok);
        cp_async8(sA + m * 400 + 256 + h * 8, g_p2h  + (gc << 4) + h, ok);
    }
    asm volatile("cp.async.commit_group;");

    if (tid < 64) {
        sBz[tid] = bxz[tid] + bhz[tid];
        sBh[tid] = bxh[tid] + bhh[tid];
    }
    if (tid < 128) sWl[tid] = Wlin[tid];

    int mw = wid >> 2, nw = wid & 3;
    int g8 = lane >> 2, t4 = lane & 3;
    int m0 = mw * 32, n0 = nw * 32;

    uint32_t b[4][2];
    #pragma unroll
    for (int nt = 0; nt < 4; ++nt) {
        int cN = n0 + nt * 8 + g8;
        b[nt][0] = __ldg(Bg + cN * A_STRW + t4);
        b[nt][1] = __ldg(Bg + cN * A_STRW + 4 + t4);
    }

    asm volatile("cp.async.wait_group 0;" ::: "memory");
    __syncthreads();

    float acc[2][4][4];
    #pragma unroll
    for (int mt = 0; mt < 2; ++mt)
        #pragma unroll
        for (int nt = 0; nt < 4; ++nt)
            #pragma unroll
            for (int e = 0; e < 4; ++e) acc[mt][nt][e] = 0.f;

    #pragma unroll
    for (int ks = 0; ks < 12; ++ks) {
        int kw = ks * 8;
        uint32_t a[2][4];
        #pragma unroll
        for (int mt = 0; mt < 2; ++mt) {
            int r0 = m0 + mt * 16;
            a[mt][0] = Au[(r0 + g8)     * A_STRW + kw + t4];
            a[mt][1] = Au[(r0 + g8 + 8) * A_STRW + kw + t4];
            a[mt][2] = Au[(r0 + g8)     * A_STRW + kw + 4 + t4];
            a[mt][3] = Au[(r0 + g8 + 8) * A_STRW + kw + 4 + t4];
        }
        uint32_t bc[4][2];
        #pragma unroll
        for (int nt = 0; nt < 4; ++nt) { bc[nt][0] = b[nt][0]; bc[nt][1] = b[nt][1]; }
        if (ks < 11) {
            int kw1 = kw + 8;
            #pragma unroll
            for (int nt = 0; nt < 4; ++nt) {
                int cN = n0 + nt * 8 + g8;
                b[nt][0] = __ldg(Bg + cN * A_STRW + kw1 + t4);
                b[nt][1] = __ldg(Bg + cN * A_STRW + kw1 + 4 + t4);
            }
        }
        #pragma unroll
        for (int mt = 0; mt < 2; ++mt)
            #pragma unroll
            for (int nt = 0; nt < 4; ++nt)
                mma16(acc[mt][nt], a[mt], bc[nt]);
    }
    __syncthreads();

    __half* Yh = (__half*)As;
    #pragma unroll
    for (int mt = 0; mt < 2; ++mt) {
        #pragma unroll
        for (int nt = 0; nt < 4; ++nt) {
            int r = m0 + mt * 16 + g8;
            int c = n0 + nt * 8 + 2 * t4;
            __half2 lo = __floats2half2_rn(acc[mt][nt][0], acc[mt][nt][1]);
            __half2 hi = __floats2half2_rn(acc[mt][nt][2], acc[mt][nt][3]);
            *(__half2*)(Yh + r * A_STRH + c)       = lo;
            *(__half2*)(Yh + (r + 8) * A_STRH + c) = hi;
        }
    }
    __syncthreads();

    // Gates via tanh.approx: z = sigmoid(cz); th = tanh((1-z)*tanh(ch))
    #pragma unroll
    for (int t = tid; t < NPB * 32; t += 256) {
        int i = t >> 5, j2 = (t & 31) * 2;
        float2 czv = __half22float2(*(__half2*)(Yh + i * A_STRH + j2));
        float2 chv = __half22float2(*(__half2*)(Yh + i * A_STRH + 64 + j2));
        float omz0 = 0.5f - 0.5f * tanh_fast(0.5f * (czv.x + sBz[j2]));
        float omz1 = 0.5f - 0.5f * tanh_fast(0.5f * (czv.y + sBz[j2 + 1]));
        float h0 = tanh_fast(chv.x + sBh[j2]);
        float h1 = tanh_fast(chv.y + sBh[j2 + 1]);
        float t0 = tanh_fast(omz0 * h0);
        float t1 = tanh_fast(omz1 * h1);
        *(__half2*)(Yh + i * A_STRH + j2) = __floats2half2_rn(t0, t1);
    }
    __syncthreads();

    if (tid < NPB * 2) {
        int i = tid >> 1, c = tid & 1;
        int g = base + i;
        if (g < n) {
            float s = blin[c];
            #pragma unroll 8
            for (int jj = 0; jj < 64; ++jj)
                s = fmaf(__half2float(Yh[i * A_STRH + jj]), sWl[2 * jj + c], s);
            out[g * 2 + c] = sigmoid_fast(s);
        }
    }
}

// ---------------------------------------------------------------------------
extern "C" void kernel_launch(void* const* d_in, const int* in_sizes, int n_in,
                              void* d_out, int out_size) {
    const float* x    = (const float*)d_in[0];
    const int*   ei   = (const int*)d_in[1];
    const float* ew   = (const float*)d_in[2];
    const float* Wxz  = (const float*)d_in[3];
    const float* bxz  = (const float*)d_in[4];
    const float* bhz  = (const float*)d_in[6];
    const float* Wxh  = (const float*)d_in[11];
    const float* bxh  = (const float*)d_in[12];
    const float* bhh  = (const float*)d_in[14];
    const float* Wlin = (const float*)d_in[15];
    const float* blin = (const float*)d_in[16];
    float* out = (float*)d_out;

    int n  = in_sizes[0] / FH;
    int ne = in_sizes[2];
    const int* row = ei;
    const int* col = ei + ne;
    int nblk  = (n + SCAN_BLK - 1) / SCAN_BLK;
    int nbDeg = (ne + 255) >> 8;
    int nbX   = (n * 16 + 255) >> 8;
    int nbG   = 148 * 6;                 // co-resident persistent gather grid

    cudaFuncSetAttribute(k_final, cudaFuncAttributeMaxDynamicSharedMemorySize, SMEM_BYTES);

    void* p_zr;  cudaGetSymbolAddress(&p_zr, g_zr);
    cudaMemsetAsync(p_zr, 0, (size_t)(2 * NN_MAX + 8) * sizeof(int), 0);

    k_prep<<<nbDeg + 96 + nbX, 256>>>(row, col, ew, ne, n, Wxz, Wxh, x);
    k_scan_scatter<<<nblk, SCAN_BLK>>>(n, nblk, row, col, ew, ne);
    k_gather2<<<nbG, 256>>>(n, nbG);
    k_final<<<(n + NPB - 1) / NPB, 256, SMEM_BYTES>>>(bxz, bhz, bxh, bhh, Wlin, blin, out, n);
}

// round 17
// speedup vs baseline: 1.1767x; 1.1767x over previous
#include <cuda_runtime.h>
#include <cuda_fp16.h>
#include <cstdint>

#define NN_MAX 50000
#define NE_MAX 800000
#define FH 64
#define SCAN_BLK 256

// Scratch. deg|cnt|sync share one zeroed region (single memset node).
__device__ int    g_zr[2 * NN_MAX + 4];
#define G_DEG  ((float*)g_zr)
#define G_CNT  (g_zr + NN_MAX)
#define G_SYNC (g_zr + 2 * NN_MAX)     // [0]=cnt1 [1]=flag1 [2]=cnt2 [3]=flag2
__device__ int    g_start[NN_MAX];
__device__ int    g_cursor[NN_MAX];
__device__ int    g_bsum[SCAN_BLK];
__device__ int    g_boff[SCAN_BLK];
__device__ float2 g_es[NE_MAX];         // (row-bits, norm) bucketed by dst col
__device__ uint2  g_xh[NN_MAX * 16];    // x as fp16
__device__ uint2  g_tx1h[NN_MAX * 16];  // tx1 as fp16
__device__ uint2  g_p2h[NN_MAX * 16];   // p2 as fp16
#define B_STRH 200
__device__ __half g_Wch[128 * B_STRH];  // combined weights fp16, [n][k]

__device__ __forceinline__ float tanh_fast(float x) {
    float y; asm("tanh.approx.f32 %0, %1;" : "=f"(y) : "f"(x)); return y;
}
__device__ __forceinline__ float sigmoid_fast(float x) {
    return fmaf(0.5f, tanh_fast(0.5f * x), 0.5f);
}
__device__ __forceinline__ uint2 pack_h4(float a, float b, float c, float d) {
    __half2 h0 = __floats2half2_rn(a, b);
    __half2 h1 = __floats2half2_rn(c, d);
    return make_uint2(*(uint32_t*)&h0, *(uint32_t*)&h1);
}
__device__ __forceinline__ float4 unpack_h4(uint2 u) {
    float2 a = __half22float2(*(__half2*)&u.x);
    float2 b = __half22float2(*(__half2*)&u.y);
    return make_float4(a.x, a.y, b.x, b.y);
}
__device__ __forceinline__ uint32_t smem_u32(const void* p) {
    uint32_t a;
    asm("{ .reg .u64 t; cvta.to.shared.u64 t, %1; cvt.u32.u64 %0, t; }" : "=r"(a) : "l"(p));
    return a;
}

// ---------------------------------------------------------------------------
// k_prep: deg/cnt histogram | fp16 weight build | x -> fp16  (wide parallel)
__global__ void k_prep(const int* __restrict__ row, const int* __restrict__ col,
                       const float* __restrict__ w, int ne, int n,
                       const float* __restrict__ Wxz, const float* __restrict__ Wxh,
                       const float* __restrict__ x) {
    int nbDeg = (ne + 255) >> 8;
    int bid = blockIdx.x;
    if (bid < nbDeg) {
        int e = bid * 256 + threadIdx.x;
        if (e < ne) {
            atomicAdd(G_DEG + row[e], w[e]);
            atomicAdd(G_CNT + col[e], 1);
        }
    } else if (bid < nbDeg + 96) {
        int t = (bid - nbDeg) * 256 + threadIdx.x;
        if (t < 192 * 128) {
            int k = t >> 7, j = t & 127;
            const float* W = (j < 64) ? Wxz : Wxh;
            int jj = j & 63;
            float v;
            if (k < 64)       v = W[k * 64 + jj] - W[2 * 4096 + k * 64 + jj];
            else if (k < 128) v = W[4096 + (k - 64) * 64 + jj];
            else              v = 2.f * W[2 * 4096 + (k - 128) * 64 + jj];
            g_Wch[j * B_STRH + k] = __float2half_rn(v);
        }
    } else {
        int t = (bid - nbDeg - 96) * 256 + threadIdx.x;
        if (t < n * 16) {
            float4 v = ((const float4*)x)[t];
            g_xh[t] = pack_h4(v.x, v.y, v.z, v.w);
        }
    }
}

// k_scan_scatter: exclusive scan of cnt -> start/cursor, grid sync, scatter.
__global__ void k_scan_scatter(int n, int nblk,
                               const int* __restrict__ row, const int* __restrict__ col,
                               const float* __restrict__ w, int ne) {
    __shared__ int s[SCAN_BLK];
    __shared__ int sl;
    int t = threadIdx.x;
    int i = blockIdx.x * SCAN_BLK + t;
    int v = (i < n) ? G_CNT[i] : 0;
    s[t] = v; __syncthreads();
    #pragma unroll
    for (int o = 1; o < SCAN_BLK; o <<= 1) {
        int u = (t >= o) ? s[t - o] : 0;
        __syncthreads(); s[t] += u; __syncthreads();
    }
    int incl = s[t];
    if (t == SCAN_BLK - 1) g_bsum[blockIdx.x] = incl;
    __threadfence();
    __syncthreads();
    if (t == 0) sl = (atomicAdd(G_SYNC + 0, 1) == nblk - 1) ? 1 : 0;
    __syncthreads();
    if (sl) {
        int bv = (t < nblk) ? g_bsum[t] : 0;
        s[t] = bv; __syncthreads();
        #pragma unroll
        for (int o = 1; o < SCAN_BLK; o <<= 1) {
            int u = (t >= o) ? s[t - o] : 0;
            __syncthreads(); s[t] += u; __syncthreads();
        }
        g_boff[t] = s[t] - bv;
        __threadfence();
        __syncthreads();
        if (t == 0) atomicExch(G_SYNC + 1, 1);
    }
    if (t == 0) { while (atomicAdd(G_SYNC + 1, 0) == 0) {} }
    __syncthreads();
    if (i < n) {
        int st = g_boff[blockIdx.x] + incl - v;
        g_start[i] = st;
        g_cursor[i] = st;
    }

    // grid sync 2, then grid-stride scatter
    __threadfence();
    __syncthreads();
    if (t == 0) {
        if (atomicAdd(G_SYNC + 2, 1) == nblk - 1) atomicExch(G_SYNC + 3, 1);
        while (atomicAdd(G_SYNC + 3, 0) == 0) {}
    }
    __syncthreads();

    int stride = nblk * SCAN_BLK;
    for (int e = blockIdx.x * SCAN_BLK + t; e < ne; e += stride) {
        int r = row[e], c = col[e];
        float dr = G_DEG[r], dc = G_DEG[c];
        float ir = dr > 0.f ? rsqrtf(dr) : 0.f;
        float ic = dc > 0.f ? rsqrtf(dc) : 0.f;
        float nm = -ir * w[e] * ic;
        int pos = atomicAdd(g_cursor + c, 1);
        g_es[pos] = make_float2(__int_as_float(r), nm);
    }
}

// Gather prop (fp16 src -> fp16 dst): 16 threads/node, uint2 loads, unroll-8.
#define G_FMA(e, u) do { \
    float4 _v = unpack_h4(u); \
    acc.x = fmaf((e).y, _v.x, acc.x); acc.y = fmaf((e).y, _v.y, acc.y); \
    acc.z = fmaf((e).y, _v.z, acc.z); acc.w = fmaf((e).y, _v.w, acc.w); } while (0)

__global__ void k_gatherh(const uint2* __restrict__ src, uint2* __restrict__ dst, int n) {
    int t = blockIdx.x * blockDim.x + threadIdx.x;
    int node = t >> 4, h = t & 15;
    if (node >= n) return;
    int beg = g_start[node], cnt = G_CNT[node];
    const float2* ep = g_es + beg;
    float4 acc = make_float4(0.f, 0.f, 0.f, 0.f);
    int k = 0;
    for (; k + 8 <= cnt; k += 8) {
        float2 e0 = ep[k],     e1 = ep[k + 1], e2 = ep[k + 2], e3 = ep[k + 3];
        float2 e4 = ep[k + 4], e5 = ep[k + 5], e6 = ep[k + 6], e7 = ep[k + 7];
        uint2 u0 = src[(__float_as_int(e0.x) << 4) + h];
        uint2 u1 = src[(__float_as_int(e1.x) << 4) + h];
        uint2 u2 = src[(__float_as_int(e2.x) << 4) + h];
        uint2 u3 = src[(__float_as_int(e3.x) << 4) + h];
        uint2 u4 = src[(__float_as_int(e4.x) << 4) + h];
        uint2 u5 = src[(__float_as_int(e5.x) << 4) + h];
        uint2 u6 = src[(__float_as_int(e6.x) << 4) + h];
        uint2 u7 = src[(__float_as_int(e7.x) << 4) + h];
        G_FMA(e0, u0); G_FMA(e1, u1); G_FMA(e2, u2); G_FMA(e3, u3);
        G_FMA(e4, u4); G_FMA(e5, u5); G_FMA(e6, u6); G_FMA(e7, u7);
    }
    for (; k < cnt; ++k) {
        float2 e0 = ep[k];
        uint2 u0 = src[(__float_as_int(e0.x) << 4) + h];
        G_FMA(e0, u0);
    }
    dst[node * 16 + h] = pack_h4(acc.x, acc.y, acc.z, acc.w);
}

// ---------------------------------------------------------------------------
// k_final: 64 nodes/block, cp.async staging; mma.m16n8k16.f16; tanh.approx gates.
#define A_STRH 200
#define A_STRW 100
#define NPB 64
#define SM_BZ   0
#define SM_BH   256
#define SM_WLIN 512
#define SM_A    1024
#define SMEM_BYTES (SM_A + NPB * A_STRH * 2)   // 26624

__device__ __forceinline__ void mma16(float* c, const uint32_t* a, const uint32_t* b) {
    asm volatile("mma.sync.aligned.m16n8k16.row.col.f32.f16.f16.f32 "
                 "{%0,%1,%2,%3}, {%4,%5,%6,%7}, {%8,%9}, {%0,%1,%2,%3};"
                 : "+f"(c[0]), "+f"(c[1]), "+f"(c[2]), "+f"(c[3])
                 : "r"(a[0]), "r"(a[1]), "r"(a[2]), "r"(a[3]), "r"(b[0]), "r"(b[1]));
}
__device__ __forceinline__ void cp_async8(uint32_t dst, const void* src, int srcsz) {
    asm volatile("cp.async.ca.shared.global [%0], [%1], 8, %2;"
                 :: "r"(dst), "l"(src), "r"(srcsz) : "memory");
}

__global__ void __launch_bounds__(256, 3)
k_final(const float* __restrict__ bxz, const float* __restrict__ bhz,
        const float* __restrict__ bxh, const float* __restrict__ bhh,
        const float* __restrict__ Wlin, const float* __restrict__ blin,
        float* __restrict__ out, int n) {
    extern __shared__ __align__(16) char smem[];
    float* sBz = (float*)(smem + SM_BZ);
    float* sBh = (float*)(smem + SM_BH);
    float* sWl = (float*)(smem + SM_WLIN);
    char*  As  = smem + SM_A;
    const uint32_t* Au = (const uint32_t*)As;
    const uint32_t* Bg = (const uint32_t*)g_Wch;

    int tid = threadIdx.x, wid = tid >> 5, lane = tid & 31;
    int blk = blockIdx.x;
    int base = blk * NPB;
    uint32_t sA = smem_u32(As);

    #pragma unroll
    for (int it = 0; it < 4; ++it) {
        int idx = tid + it * 256;
        int m = idx >> 4, h = idx & 15;
        int g = base + m;
        int ok = (g < n) ? 8 : 0;
        int gc = (g < n) ? g : 0;
        cp_async8(sA + m * 400 + h * 8,       g_xh   + (gc << 4) + h, ok);
        cp_async8(sA + m * 400 + 128 + h * 8, g_tx1h + (gc << 4) + h, ok);
        cp_async8(sA + m * 400 + 256 + h * 8, g_p2h  + (gc << 4) + h, ok);
    }
    asm volatile("cp.async.commit_group;");

    if (tid < 64) {
        sBz[tid] = bxz[tid] + bhz[tid];
        sBh[tid] = bxh[tid] + bhh[tid];
    }
    if (tid < 128) sWl[tid] = Wlin[tid];

    int mw = wid >> 2, nw = wid & 3;
    int g8 = lane >> 2, t4 = lane & 3;
    int m0 = mw * 32, n0 = nw * 32;

    uint32_t b[4][2];
    #pragma unroll
    for (int nt = 0; nt < 4; ++nt) {
        int cN = n0 + nt * 8 + g8;
        b[nt][0] = __ldg(Bg + cN * A_STRW + t4);
        b[nt][1] = __ldg(Bg + cN * A_STRW + 4 + t4);
    }

    asm volatile("cp.async.wait_group 0;" ::: "memory");
    __syncthreads();

    float acc[2][4][4];
    #pragma unroll
    for (int mt = 0; mt < 2; ++mt)
        #pragma unroll
        for (int nt = 0; nt < 4; ++nt)
            #pragma unroll
            for (int e = 0; e < 4; ++e) acc[mt][nt][e] = 0.f;

    #pragma unroll
    for (int ks = 0; ks < 12; ++ks) {
        int kw = ks * 8;
        uint32_t a[2][4];
        #pragma unroll
        for (int mt = 0; mt < 2; ++mt) {
            int r0 = m0 + mt * 16;
            a[mt][0] = Au[(r0 + g8)     * A_STRW + kw + t4];
            a[mt][1] = Au[(r0 + g8 + 8) * A_STRW + kw + t4];
            a[mt][2] = Au[(r0 + g8)     * A_STRW + kw + 4 + t4];
            a[mt][3] = Au[(r0 + g8 + 8) * A_STRW + kw + 4 + t4];
        }
        uint32_t bc[4][2];
        #pragma unroll
        for (int nt = 0; nt < 4; ++nt) { bc[nt][0] = b[nt][0]; bc[nt][1] = b[nt][1]; }
        if (ks < 11) {
            int kw1 = kw + 8;
            #pragma unroll
            for (int nt = 0; nt < 4; ++nt) {
                int cN = n0 + nt * 8 + g8;
                b[nt][0] = __ldg(Bg + cN * A_STRW + kw1 + t4);
                b[nt][1] = __ldg(Bg + cN * A_STRW + kw1 + 4 + t4);
            }
        }
        #pragma unroll
        for (int mt = 0; mt < 2; ++mt)
            #pragma unroll
            for (int nt = 0; nt < 4; ++nt)
                mma16(acc[mt][nt], a[mt], bc[nt]);
    }
    __syncthreads();

    __half* Yh = (__half*)As;
    #pragma unroll
    for (int mt = 0; mt < 2; ++mt) {
        #pragma unroll
        for (int nt = 0; nt < 4; ++nt) {
            int r = m0 + mt * 16 + g8;
            int c = n0 + nt * 8 + 2 * t4;
            __half2 lo = __floats2half2_rn(acc[mt][nt][0], acc[mt][nt][1]);
            __half2 hi = __floats2half2_rn(acc[mt][nt][2], acc[mt][nt][3]);
            *(__half2*)(Yh + r * A_STRH + c)       = lo;
            *(__half2*)(Yh + (r + 8) * A_STRH + c) = hi;
        }
    }
    __syncthreads();

    // Gates via tanh.approx: (1-z) = 0.5 - 0.5*tanh(cz/2); th = tanh((1-z)*tanh(ch))
    #pragma unroll
    for (int t = tid; t < NPB * 32; t += 256) {
        int i = t >> 5, j2 = (t & 31) * 2;
        float2 czv = __half22float2(*(__half2*)(Yh + i * A_STRH + j2));
        float2 chv = __half22float2(*(__half2*)(Yh + i * A_STRH + 64 + j2));
        float omz0 = 0.5f - 0.5f * tanh_fast(0.5f * (czv.x + sBz[j2]));
        float omz1 = 0.5f - 0.5f * tanh_fast(0.5f * (czv.y + sBz[j2 + 1]));
        float h0 = tanh_fast(chv.x + sBh[j2]);
        float h1 = tanh_fast(chv.y + sBh[j2 + 1]);
        float t0 = tanh_fast(omz0 * h0);
        float t1 = tanh_fast(omz1 * h1);
        *(__half2*)(Yh + i * A_STRH + j2) = __floats2half2_rn(t0, t1);
    }
    __syncthreads();

    if (tid < NPB * 2) {
        int i = tid >> 1, c = tid & 1;
        int g = base + i;
        if (g < n) {
            float s = blin[c];
            #pragma unroll 8
            for (int jj = 0; jj < 64; ++jj)
                s = fmaf(__half2float(Yh[i * A_STRH + jj]), sWl[2 * jj + c], s);
            out[g * 2 + c] = sigmoid_fast(s);
        }
    }
}

// ---------------------------------------------------------------------------
extern "C" void kernel_launch(void* const* d_in, const int* in_sizes, int n_in,
                              void* d_out, int out_size) {
    const float* x    = (const float*)d_in[0];
    const int*   ei   = (const int*)d_in[1];
    const float* ew   = (const float*)d_in[2];
    const float* Wxz  = (const float*)d_in[3];
    const float* bxz  = (const float*)d_in[4];
    const float* bhz  = (const float*)d_in[6];
    const float* Wxh  = (const float*)d_in[11];
    const float* bxh  = (const float*)d_in[12];
    const float* bhh  = (const float*)d_in[14];
    const float* Wlin = (const float*)d_in[15];
    const float* blin = (const float*)d_in[16];
    float* out = (float*)d_out;

    int n  = in_sizes[0] / FH;
    int ne = in_sizes[2];
    const int* row = ei;
    const int* col = ei + ne;
    int nblk  = (n + SCAN_BLK - 1) / SCAN_BLK;
    int nbDeg = (ne + 255) >> 8;
    int nbX   = (n * 16 + 255) >> 8;

    cudaFuncSetAttribute(k_final, cudaFuncAttributeMaxDynamicSharedMemorySize, SMEM_BYTES);

    void* p_zr;  cudaGetSymbolAddress(&p_zr, g_zr);
    cudaMemsetAsync(p_zr, 0, (size_t)(2 * NN_MAX + 4) * sizeof(int), 0);

    uint2 *p_xh, *p_tx1h, *p_p2h;
    cudaGetSymbolAddress((void**)&p_xh, g_xh);
    cudaGetSymbolAddress((void**)&p_tx1h, g_tx1h);
    cudaGetSymbolAddress((void**)&p_p2h, g_p2h);

    k_prep<<<nbDeg + 96 + nbX, 256>>>(row, col, ew, ne, n, Wxz, Wxh, x);
    k_scan_scatter<<<nblk, SCAN_BLK>>>(n, nblk, row, col, ew, ne);
    k_gatherh<<<(n * 16 + 255) / 256, 256>>>(p_xh, p_tx1h, n);
    k_gatherh<<<(n * 16 + 255) / 256, 256>>>(p_tx1h, p_p2h, n);
    k_final<<<(n + NPB - 1) / NPB, 256, SMEM_BYTES>>>(bxz, bhz, bxh, bhh, Wlin, blin, out, n);
}